// round 6
// baseline (speedup 1.0000x reference)
#include <cuda_runtime.h>

// Fused SfmPool: softmax pooling, window 3x3, stride 2, SAME, T=1.
// Input:  value [32,128,128,192] fp32 NHWC   Output: [32,64,64,192] fp32
//
// Single kernel. Per block (4x4 output tile x 192 channels):
//  Phase A: cooperatively compute the 6x6 neighborhood of 3x3/stride-2 window
//           maxes M into shared memory (OOB output cells stored as 0 — they are
//           never members of a coverage set, so adding 0 is identity).
//  Phase B: per output, max_v per input element = sum of M over covering windows
//           (coverage per axis: coord 0 -> {0}; odd -> {c/2}; even>0 -> {c/2-1, c/2}),
//           then out = sum(v*exp(v-max_v)) / sum(exp(v-max_v)), pad cells skipped.

namespace {
constexpr int Bn  = 32;
constexpr int H   = 128;
constexpr int W   = 128;
constexpr int C2  = 96;    // 192 channels as float2 lanes
constexpr int OH  = 64;
constexpr int OW  = 64;
constexpr int OYT = 4;     // output rows per block
constexpr int OXT = 4;     // output cols per block
constexpr int MG  = OYT + 2;   // 6 M rows in smem
constexpr int MK  = OXT + 2;   // 6 M cols in smem
constexpr int TX  = C2;        // 96
constexpr int TY  = OXT;       // 4
constexpr int TPB = TX * TY;   // 384
constexpr int MJOBS = MG * MK * C2;     // 3456 = 9 * TPB exactly
}

__device__ __forceinline__ float2 f2max(float2 a, float2 b) {
    return make_float2(fmaxf(a.x, b.x), fmaxf(a.y, b.y));
}
__device__ __forceinline__ float2 f2add(float2 a, float2 b) {
    return make_float2(a.x + b.x, a.y + b.y);
}

__global__ void __launch_bounds__(TPB, 4) fused_sfm_k(const float2* __restrict__ x,
                                                      float2* __restrict__ out) {
    __shared__ float2 sM[MG * MK * C2];   // 27,648 B

    const int tx = threadIdx.x;            // c2 lane, 0..95
    const int ty = threadIdx.y;            // 0..3
    const int tid = ty * TX + tx;
    const int oxBase = blockIdx.x * OXT;
    const int oyBase = blockIdx.y * OYT;
    const int b = blockIdx.z;

    const float2* __restrict__ xb0 = x + (b * H * W) * C2;
    const float NEG_INF = __int_as_float(0xff800000);

    // ---------------- Phase A: M tile -> smem (each cell computed once) ----------------
    #pragma unroll
    for (int it = 0; it < MJOBS / TPB; ++it) {    // 9 iterations, exact
        int job  = it * TPB + tid;
        int c2   = job % C2;                      // fastest -> coalesced loads
        int cell = job / C2;                      // 0..35
        int kx   = cell % MK;
        int g    = cell / MK;
        int OY = oyBase + g - 1;
        int OX = oxBase + kx - 1;

        float2 m = make_float2(0.f, 0.f);         // OOB output cell -> 0
        if ((unsigned)OY < (unsigned)OH && (unsigned)OX < (unsigned)OW) {
            int y0 = OY * 2, x0 = OX * 2;
            m = make_float2(NEG_INF, NEG_INF);
            #pragma unroll
            for (int j = 0; j < 3; j++) {
                int y = y0 + j;
                if (y < H) {
                    const float2* __restrict__ row = xb0 + (y * W) * C2 + c2;
                    #pragma unroll
                    for (int i = 0; i < 3; i++) {
                        int xx = x0 + i;
                        if (xx < W) m = f2max(m, row[xx * C2]);
                    }
                }
            }
        }
        sM[cell * C2 + c2] = m;
    }
    __syncthreads();

    // ---------------- Phase B: 4 outputs per thread ----------------
    const int c2  = tx;
    const int OXo = oxBase + ty;                  // global output col for this thread
    const int x0  = OXo * 2;
    const float2* __restrict__ xc = xb0 + c2;
    float2* __restrict__ ob = out + ((b * OH) * OW) * C2 + c2;
    const float LOG2E = 1.4426950408889634f;
    const float2 z = make_float2(0.f, 0.f);

    #pragma unroll
    for (int r = 0; r < OYT; ++r) {
        const int OYo = oyBase + r;
        const int y0  = OYo * 2;

        // Column-coverage sums per M row gg (M rows r..r+2 ↔ output rows OYo-1..OYo+1):
        //   A[gg][0] = M[gg][ty]   + M[gg][ty+1]   (even col x0,    windows {OXo-1, OXo})
        //   A[gg][1] = M[gg][ty+1]                 (odd col x0+1,   window  {OXo})
        //   A[gg][2] = M[gg][ty+1] + M[gg][ty+2]   (even col x0+2,  windows {OXo, OXo+1})
        float2 A[3][3];
        #pragma unroll
        for (int gg = 0; gg < 3; gg++) {
            const float2* Mr = &sM[((r + gg) * MK + ty) * C2 + c2];
            float2 m0 = Mr[0 * C2];
            float2 m1 = Mr[1 * C2];
            float2 m2 = Mr[2 * C2];
            A[gg][0] = f2add(m0, m1);
            A[gg][1] = m1;
            A[gg][2] = f2add(m1, m2);
        }

        float2 num = z, den = z;
        #pragma unroll
        for (int j = 0; j < 3; j++) {
            int y = y0 + j;
            bool vy = (y < H);
            int yc = vy ? y : (H - 1);
            const float2* __restrict__ row = xc + (yc * W) * C2;
            #pragma unroll
            for (int i = 0; i < 3; i++) {
                int xx = x0 + i;
                bool ok = vy && (xx < W);
                int xcl = (xx < W) ? xx : (W - 1);
                float2 v = row[xcl * C2];
                // Row coverage: j=0 (even) -> M rows {r, r+1}; j=1 (odd) -> {r+1};
                //               j=2 (even) -> {r+1, r+2}. OOB rows already zeroed in M.
                float2 mv;
                if (j == 0)      mv = f2add(A[0][i], A[1][i]);
                else if (j == 1) mv = A[1][i];
                else             mv = f2add(A[1][i], A[2][i]);

                float ex;
                ex = ok ? exp2f((v.x - mv.x) * LOG2E) : 0.f;
                den.x += ex; num.x = fmaf(v.x, ex, num.x);
                ex = ok ? exp2f((v.y - mv.y) * LOG2E) : 0.f;
                den.y += ex; num.y = fmaf(v.y, ex, num.y);
            }
        }
        ob[(OYo * OW + OXo) * C2] = make_float2(__fdividef(num.x, den.x),
                                                __fdividef(num.y, den.y));
    }
}

extern "C" void kernel_launch(void* const* d_in, const int* in_sizes, int n_in,
                              void* d_out, int out_size) {
    (void)in_sizes; (void)n_in; (void)out_size;
    const float2* x = (const float2*)d_in[0];
    float2* out = (float2*)d_out;
    dim3 block(TX, TY, 1);                           // 384 threads
    dim3 grid(OW / OXT, OH / OYT, Bn);               // 16 x 16 x 32 = 8192 blocks
    fused_sfm_k<<<grid, block>>>(x, out);
}

// round 7
// speedup vs baseline: 1.0030x; 1.0030x over previous
#include <cuda_runtime.h>

// Fused SfmPool: softmax pooling, window 3x3, stride 2, SAME, T=1.
// Input:  value [32,128,128,192] fp32 NHWC   Output: [32,64,64,192] fp32
//
// Single kernel. Per block (4x4 output tile x 192 channels):
//  Phase A: cooperatively compute the 6x6 neighborhood of 3x3/stride-2 window
//           maxes M into shared memory (OOB output cells stored as 0 — they are
//           never members of a coverage set, so adding 0 is identity).
//  Phase B: per output, max_v per input element = sum of M over covering windows
//           (coverage per axis: coord 0 -> {0}; odd -> {c/2}; even>0 -> {c/2-1, c/2}),
//           then out = sum(v*exp(v-max_v)) / sum(exp(v-max_v)), pad cells skipped.

namespace {
constexpr int Bn  = 32;
constexpr int H   = 128;
constexpr int W   = 128;
constexpr int C2  = 96;    // 192 channels as float2 lanes
constexpr int OH  = 64;
constexpr int OW  = 64;
constexpr int OYT = 4;     // output rows per block
constexpr int OXT = 4;     // output cols per block
constexpr int MG  = OYT + 2;   // 6 M rows in smem
constexpr int MK  = OXT + 2;   // 6 M cols in smem
constexpr int TX  = C2;        // 96
constexpr int TY  = OXT;       // 4
constexpr int TPB = TX * TY;   // 384
constexpr int MJOBS = MG * MK * C2;     // 3456 = 9 * TPB exactly
}

__device__ __forceinline__ float2 f2max(float2 a, float2 b) {
    return make_float2(fmaxf(a.x, b.x), fmaxf(a.y, b.y));
}
__device__ __forceinline__ float2 f2add(float2 a, float2 b) {
    return make_float2(a.x + b.x, a.y + b.y);
}

__global__ void __launch_bounds__(TPB, 4) fused_sfm_k(const float2* __restrict__ x,
                                                      float2* __restrict__ out) {
    __shared__ float2 sM[MG * MK * C2];   // 27,648 B

    const int tx = threadIdx.x;            // c2 lane, 0..95
    const int ty = threadIdx.y;            // 0..3
    const int tid = ty * TX + tx;
    const int oxBase = blockIdx.x * OXT;
    const int oyBase = blockIdx.y * OYT;
    const int b = blockIdx.z;

    const float2* __restrict__ xb0 = x + (b * H * W) * C2;
    const float NEG_INF = __int_as_float(0xff800000);

    // ---------------- Phase A: M tile -> smem (each cell computed once) ----------------
    #pragma unroll
    for (int it = 0; it < MJOBS / TPB; ++it) {    // 9 iterations, exact
        int job  = it * TPB + tid;
        int c2   = job % C2;                      // fastest -> coalesced loads
        int cell = job / C2;                      // 0..35
        int kx   = cell % MK;
        int g    = cell / MK;
        int OY = oyBase + g - 1;
        int OX = oxBase + kx - 1;

        float2 m = make_float2(0.f, 0.f);         // OOB output cell -> 0
        if ((unsigned)OY < (unsigned)OH && (unsigned)OX < (unsigned)OW) {
            int y0 = OY * 2, x0 = OX * 2;
            m = make_float2(NEG_INF, NEG_INF);
            #pragma unroll
            for (int j = 0; j < 3; j++) {
                int y = y0 + j;
                if (y < H) {
                    const float2* __restrict__ row = xb0 + (y * W) * C2 + c2;
                    #pragma unroll
                    for (int i = 0; i < 3; i++) {
                        int xx = x0 + i;
                        if (xx < W) m = f2max(m, row[xx * C2]);
                    }
                }
            }
        }
        sM[cell * C2 + c2] = m;
    }
    __syncthreads();

    // ---------------- Phase B: 4 outputs per thread ----------------
    const int c2  = tx;
    const int OXo = oxBase + ty;                  // global output col for this thread
    const int x0  = OXo * 2;
    const float2* __restrict__ xc = xb0 + c2;
    float2* __restrict__ ob = out + ((b * OH) * OW) * C2 + c2;
    const float LOG2E = 1.4426950408889634f;
    const float2 z = make_float2(0.f, 0.f);

    #pragma unroll
    for (int r = 0; r < OYT; ++r) {
        const int OYo = oyBase + r;
        const int y0  = OYo * 2;

        // Column-coverage sums per M row gg (M rows r..r+2 ↔ output rows OYo-1..OYo+1):
        //   A[gg][0] = M[gg][ty]   + M[gg][ty+1]   (even col x0,    windows {OXo-1, OXo})
        //   A[gg][1] = M[gg][ty+1]                 (odd col x0+1,   window  {OXo})
        //   A[gg][2] = M[gg][ty+1] + M[gg][ty+2]   (even col x0+2,  windows {OXo, OXo+1})
        float2 A[3][3];
        #pragma unroll
        for (int gg = 0; gg < 3; gg++) {
            const float2* Mr = &sM[((r + gg) * MK + ty) * C2 + c2];
            float2 m0 = Mr[0 * C2];
            float2 m1 = Mr[1 * C2];
            float2 m2 = Mr[2 * C2];
            A[gg][0] = f2add(m0, m1);
            A[gg][1] = m1;
            A[gg][2] = f2add(m1, m2);
        }

        float2 num = z, den = z;
        #pragma unroll
        for (int j = 0; j < 3; j++) {
            int y = y0 + j;
            bool vy = (y < H);
            int yc = vy ? y : (H - 1);
            const float2* __restrict__ row = xc + (yc * W) * C2;
            #pragma unroll
            for (int i = 0; i < 3; i++) {
                int xx = x0 + i;
                bool ok = vy && (xx < W);
                int xcl = (xx < W) ? xx : (W - 1);
                float2 v = row[xcl * C2];
                // Row coverage: j=0 (even) -> M rows {r, r+1}; j=1 (odd) -> {r+1};
                //               j=2 (even) -> {r+1, r+2}. OOB rows already zeroed in M.
                float2 mv;
                if (j == 0)      mv = f2add(A[0][i], A[1][i]);
                else if (j == 1) mv = A[1][i];
                else             mv = f2add(A[1][i], A[2][i]);

                float ex;
                ex = ok ? exp2f((v.x - mv.x) * LOG2E) : 0.f;
                den.x += ex; num.x = fmaf(v.x, ex, num.x);
                ex = ok ? exp2f((v.y - mv.y) * LOG2E) : 0.f;
                den.y += ex; num.y = fmaf(v.y, ex, num.y);
            }
        }
        ob[(OYo * OW + OXo) * C2] = make_float2(__fdividef(num.x, den.x),
                                                __fdividef(num.y, den.y));
    }
}

extern "C" void kernel_launch(void* const* d_in, const int* in_sizes, int n_in,
                              void* d_out, int out_size) {
    (void)in_sizes; (void)n_in; (void)out_size;
    const float2* x = (const float2*)d_in[0];
    float2* out = (float2*)d_out;
    dim3 block(TX, TY, 1);                           // 384 threads
    dim3 grid(OW / OXT, OH / OYT, Bn);               // 16 x 16 x 32 = 8192 blocks
    fused_sfm_k<<<grid, block>>>(x, out);
}